// round 12
// baseline (speedup 1.0000x reference)
#include <cuda_runtime.h>
#include <math.h>

// Problem constants
#define NH     16      // N = B*H
#define TT     1024    // T
#define DIM    64
#define DM     512     // D model
#define LT     4       // tables
#define KBITS  3
#define RB     8       // buckets per table
#define SB     32      // total buckets
#define NC     32      // chunks
#define CH     32      // chunk length (NC*CH = T)

// Scratch (static device globals: no allocation allowed)
__device__ float g_Qf[NH * TT * DIM];
__device__ float g_Kf[NH * TT * DIM];
__device__ float g_Vf[NH * TT * DIM];
__device__ float g_assign[NH * TT * SB];
__device__ float g_preK[NH * NC * SB * DIM];
__device__ float g_preV[NH * NC * SB * DIM];
__device__ float g_preD[NH * NC * SB];
__device__ float g_att[2 * TT * DM];

// Packed dual-FMA: each lane is an independent IEEE fma.rn -> bitwise
// identical to two scalar __fmaf_rn with the same accumulation order.
#define FFMA2(d, a, b, c) \
    asm("fma.rn.f32x2 %0, %1, %2, %3;" : "=l"(d) : "l"(a), "l"(b), "l"(c))
#define BCAST2(d, f) \
    asm("mov.b64 %0, {%1, %1};" : "=l"(d) : "f"(f))

// ---------------------------------------------------------------------------
// XLA-CPU exp(f32): Cephes-style approximation (GenerateVF32Exp).
// ---------------------------------------------------------------------------
__device__ __forceinline__ float xla_exp(float input)
{
    const float exp_hi = 88.3762626647950f;
    const float exp_lo = -88.3762626647949f;
    float xc = fminf(fmaxf(input, exp_lo), exp_hi);
    float fx = floorf(__fmaf_rn(xc, 1.44269504088896341f, 0.5f));
    float tmp = __fmul_rn(fx, 0.693359375f);
    float z   = __fmul_rn(fx, -2.12194440e-4f);
    float x   = __fsub_rn(xc, tmp);
    x         = __fsub_rn(x, z);
    z         = __fmul_rn(x, x);
    float y = __fmaf_rn(x, 1.9875691500e-4f, 1.3981999507e-3f);
    y = __fmaf_rn(y, x, 8.3334519073e-3f);
    y = __fmaf_rn(y, x, 4.1665795894e-2f);
    y = __fmaf_rn(y, x, 1.6666665459e-1f);
    y = __fmaf_rn(y, x, 5.0000001201e-1f);
    y = __fmaf_rn(y, z, x);
    y = __fadd_rn(y, 1.0f);
    int n = (int)fx;
    float scale = __int_as_float((n + 127) << 23);
    return __fmul_rn(y, scale);
}

// ---------------------------------------------------------------------------
// XLA EmitFastTanh with_fma=true (Eigen ptanh pairing): clamp
// +/-7.99881172180175781, FMA Horner, |x|<0.0004 passthrough.
// CONFIRMED (R9 pass): this is the reference's tanh variant.
// ---------------------------------------------------------------------------
__device__ __forceinline__ float xla_tanh(float x)
{
    const float kClamp = 7.99881172180175781f;
    if (fabsf(x) < 0.0004f) return x;
    float xc = fminf(fmaxf(x, -kClamp), kClamp);
    float x2 = __fmul_rn(xc, xc);
    float np = -2.76076847742355e-16f;
    np = __fmaf_rn(np, x2, 2.00018790482477e-13f);
    np = __fmaf_rn(np, x2, -8.60467152213735e-11f);
    np = __fmaf_rn(np, x2, 5.12229709037114e-08f);
    np = __fmaf_rn(np, x2, 1.48572235717979e-05f);
    np = __fmaf_rn(np, x2, 6.37261928875436e-04f);
    np = __fmaf_rn(np, x2, 4.89352455891786e-03f);
    float num = __fmul_rn(xc, np);
    float dp = 1.19825839466702e-06f;
    dp = __fmaf_rn(dp, x2, 1.18534705686654e-04f);
    dp = __fmaf_rn(dp, x2, 2.26843463243900e-03f);
    dp = __fmaf_rn(dp, x2, 4.89352518554385e-03f);
    return __fdiv_rn(num, dp);
}

// ---------------------------------------------------------------------------
// GEMM 1: fused QKV projection, FFMA2 version (unchanged from R11).
// ---------------------------------------------------------------------------
__global__ __launch_bounds__(256) void gemm_qkv_kernel(
    const float* __restrict__ x,
    const float* __restrict__ Wq,
    const float* __restrict__ Wk,
    const float* __restrict__ Wv)
{
    __shared__ __align__(16) float As[16][132];
    __shared__ float Bs[16][68];

    const int j0 = blockIdx.x * 64;     // 0..1535
    const int m0 = blockIdx.y * 128;    // 0..1920
    const int wsel = j0 >> 9;
    const float* W;
    float* outp;
    if (wsel == 0)      { W = Wq; outp = g_Qf; }
    else if (wsel == 1) { W = Wk; outp = g_Kf; }
    else                { W = Wv; outp = g_Vf; }
    const int jj0 = j0 & 511;

    const int tid = threadIdx.x;
    const int tx = tid & 15;
    const int ty = tid >> 4;

    unsigned long long acc2[4][4];
#pragma unroll
    for (int ip = 0; ip < 4; ip++)
#pragma unroll
        for (int j = 0; j < 4; j++) acc2[ip][j] = 0ULL;

    for (int k0 = 0; k0 < 512; k0 += 16) {
#pragma unroll
        for (int i = 0; i < 8; i++) {
            int idx = tid + i * 256;
            int r = idx >> 4;
            int kk = idx & 15;
            As[kk][r] = x[(m0 + r) * 512 + k0 + kk];
        }
#pragma unroll
        for (int i = 0; i < 4; i++) {
            int idx = tid + i * 256;
            int r = idx >> 4;
            int kk = idx & 15;
            Bs[kk][r] = W[(jj0 + r) * 512 + k0 + kk];
        }
        __syncthreads();
#pragma unroll
        for (int kk = 0; kk < 16; kk++) {
            ulonglong2 a01 = *(const ulonglong2*)&As[kk][ty * 8];
            ulonglong2 a23 = *(const ulonglong2*)&As[kk][ty * 8 + 4];
            unsigned long long ap[4] = {a01.x, a01.y, a23.x, a23.y};
#pragma unroll
            for (int j = 0; j < 4; j++) {
                float bj = Bs[kk][tx * 4 + j];
                unsigned long long bb;
                BCAST2(bb, bj);
#pragma unroll
                for (int ip = 0; ip < 4; ip++)
                    FFMA2(acc2[ip][j], ap[ip], bb, acc2[ip][j]);
            }
        }
        __syncthreads();
    }

#pragma unroll
    for (int ip = 0; ip < 4; ip++) {
#pragma unroll
        for (int j = 0; j < 4; j++) {
            float lo = __uint_as_float((unsigned int)(acc2[ip][j] & 0xffffffffULL));
            float hi = __uint_as_float((unsigned int)(acc2[ip][j] >> 32));
            int jc = jj0 + tx * 4 + j;
            int h = jc >> 6;
            int d = jc & 63;
            int m_lo = m0 + ty * 8 + 2 * ip;
            outp[(((m_lo >> 10) * 8 + h) * TT + (m_lo & 1023)) * DIM + d] = lo;
            int m_hi = m_lo + 1;
            outp[(((m_hi >> 10) * 8 + h) * TT + (m_hi & 1023)) * DIM + d] = hi;
        }
    }
}

// ---------------------------------------------------------------------------
// GEMM 2: final output projection, FFMA2 version (unchanged from R11).
// ---------------------------------------------------------------------------
__global__ __launch_bounds__(256) void gemm_out_kernel(
    const float* __restrict__ Wout,
    const float* __restrict__ bout,
    float* __restrict__ out)
{
    __shared__ __align__(16) float As[16][132];
    __shared__ float Bs[16][68];

    const int j0 = blockIdx.x * 64;
    const int m0 = blockIdx.y * 128;
    const int tid = threadIdx.x;
    const int tx = tid & 15;
    const int ty = tid >> 4;

    unsigned long long acc2[4][4];
#pragma unroll
    for (int ip = 0; ip < 4; ip++)
#pragma unroll
        for (int j = 0; j < 4; j++) acc2[ip][j] = 0ULL;

    for (int k0 = 0; k0 < 512; k0 += 16) {
#pragma unroll
        for (int i = 0; i < 8; i++) {
            int idx = tid + i * 256;
            int r = idx >> 4;
            int kk = idx & 15;
            As[kk][r] = g_att[(m0 + r) * 512 + k0 + kk];
        }
#pragma unroll
        for (int i = 0; i < 4; i++) {
            int idx = tid + i * 256;
            int r = idx >> 4;
            int kk = idx & 15;
            Bs[kk][r] = Wout[(j0 + r) * 512 + k0 + kk];
        }
        __syncthreads();
#pragma unroll
        for (int kk = 0; kk < 16; kk++) {
            ulonglong2 a01 = *(const ulonglong2*)&As[kk][ty * 8];
            ulonglong2 a23 = *(const ulonglong2*)&As[kk][ty * 8 + 4];
            unsigned long long ap[4] = {a01.x, a01.y, a23.x, a23.y};
#pragma unroll
            for (int j = 0; j < 4; j++) {
                float bj = Bs[kk][tx * 4 + j];
                unsigned long long bb;
                BCAST2(bb, bj);
#pragma unroll
                for (int ip = 0; ip < 4; ip++)
                    FFMA2(acc2[ip][j], ap[ip], bb, acc2[ip][j]);
            }
        }
        __syncthreads();
    }

#pragma unroll
    for (int ip = 0; ip < 4; ip++) {
#pragma unroll
        for (int j = 0; j < 4; j++) {
            int jc = j0 + tx * 4 + j;
            float bb = bout[jc];
            float lo = __uint_as_float((unsigned int)(acc2[ip][j] & 0xffffffffULL));
            float hi = __uint_as_float((unsigned int)(acc2[ip][j] >> 32));
            int m_lo = m0 + ty * 8 + 2 * ip;
            out[m_lo * 512 + jc]       = __fadd_rn(lo, bb);
            out[(m_lo + 1) * 512 + jc] = __fadd_rn(hi, bb);
        }
    }
}

// ---------------------------------------------------------------------------
// Phase 2: LSH bucket assignment — one thread per (n,t), all 4 tables.
// K row via 16 LDG.128 (loaded ONCE, vs 4x scalar before); planes+protos
// staged in smem (warp-broadcast LDS). The 12 accumulation chains are the
// same ascending-d fma chains as before -> bit-identical selections.
// ---------------------------------------------------------------------------
__global__ __launch_bounds__(256) void assign_kernel(
    const float* __restrict__ planes_T,   // [64][12] row-major
    const float* __restrict__ protos_T,   // [3][8]
    const float* __restrict__ logit_temp) // scalar
{
    __shared__ float s_pl[64 * 12];
    __shared__ float s_proto[24];
    const int tid = threadIdx.x;
    for (int i = tid; i < 64 * 12; i += 256) s_pl[i] = planes_T[i];
    if (tid < 24) s_proto[tid] = protos_T[tid];
    __syncthreads();

    const int gid = blockIdx.x * 256 + tid;   // 0..16383
    const int n = gid >> 10;
    const int t = gid & 1023;

    float scale = xla_exp(logit_temp[0]);
    scale = fminf(fmaxf(scale, 0.01f), 20.0f);

    const float4* K4 = (const float4*)(g_Kf + (n * TT + t) * DIM);
    float s[12];
#pragma unroll
    for (int j = 0; j < 12; j++) s[j] = 0.f;

#pragma unroll
    for (int d4 = 0; d4 < 16; d4++) {
        float4 kv4 = K4[d4];
        float kv[4] = {kv4.x, kv4.y, kv4.z, kv4.w};
#pragma unroll
        for (int q = 0; q < 4; q++) {
            const float* pl = s_pl + (d4 * 4 + q) * 12;
#pragma unroll
            for (int j = 0; j < 12; j++)
                s[j] = __fmaf_rn(kv[q], pl[j], s[j]);
        }
    }

    float* outrow = g_assign + (n * TT + t) * SB;
#pragma unroll
    for (int l = 0; l < LT; l++) {
        float t0 = __fdiv_rn(xla_tanh(s[l * 3 + 0]), scale);
        float t1 = __fdiv_rn(xla_tanh(s[l * 3 + 1]), scale);
        float t2 = __fdiv_rn(xla_tanh(s[l * 3 + 2]), scale);

        float logits[RB];
        float mx = -1e30f;
#pragma unroll
        for (int r = 0; r < RB; r++) {
            float lg = __fmaf_rn(t2, s_proto[16 + r],
                       __fmaf_rn(t1, s_proto[8 + r],
                                 __fmul_rn(t0, s_proto[r])));
            logits[r] = lg;
            mx = fmaxf(mx, lg);
        }
        float e[RB];
        float sum = 0.f;
#pragma unroll
        for (int r = 0; r < RB; r++) {
            e[r] = xla_exp(__fsub_rn(logits[r], mx));
            sum = __fadd_rn(sum, e[r]);
        }
        float p[RB];
#pragma unroll
        for (int r = 0; r < RB; r++) p[r] = __fdiv_rn(e[r], sum);

        int i1 = 0; float p1 = p[0];
#pragma unroll
        for (int r = 1; r < RB; r++) { if (p[r] > p1) { p1 = p[r]; i1 = r; } }
        int i2 = -1; float p2 = -1.f;
#pragma unroll
        for (int r = 0; r < RB; r++) { if (r != i1 && p[r] > p2) { p2 = p[r]; i2 = r; } }

        float denom = __fadd_rn(__fadd_rn(p1, p2), 1e-6f);
        float* outp = outrow + l * RB;
#pragma unroll
        for (int r = 0; r < RB; r++) outp[r] = 0.f;
        outp[i1] = __fdiv_rn(p1, denom);
        outp[i2] = __fdiv_rn(p2, denom);
    }
}

// ---------------------------------------------------------------------------
// Phase 3a: per-chunk bucket-state partial sums, with t+1 prefetch.
// Unconditional update: adding a*k when a==0 adds +/-0 which is the identity
// (accumulator can never be -0), bit-identical to the guarded version.
// ---------------------------------------------------------------------------
__global__ __launch_bounds__(256) void chunksum_kernel()
{
    const int c = blockIdx.x;
    const int n = blockIdx.y;
    const int tid = threadIdx.x;
    const int s = tid >> 3;
    const int g = tid & 7;

    float aK[8], aV[8];
#pragma unroll
    for (int j = 0; j < 8; j++) { aK[j] = 0.f; aV[j] = 0.f; }
    float den = 0.f;

    const int t0 = c * CH;
    // prefetch t0
    float pa = g_assign[(n * TT + t0) * SB + s];
    const float* Kp0 = g_Kf + (n * TT + t0) * DIM + g * 8;
    const float* Vp0 = g_Vf + (n * TT + t0) * DIM + g * 8;
    float4 pk1 = *(const float4*)Kp0, pk2 = *(const float4*)(Kp0 + 4);
    float4 pv1 = *(const float4*)Vp0, pv2 = *(const float4*)(Vp0 + 4);

    for (int tt = 0; tt < CH; tt++) {
        float a = pa;
        float4 k1 = pk1, k2 = pk2, v1 = pv1, v2 = pv2;
        if (tt + 1 < CH) {
            const int t = t0 + tt + 1;
            pa = g_assign[(n * TT + t) * SB + s];
            const float* Kp = g_Kf + (n * TT + t) * DIM + g * 8;
            const float* Vp = g_Vf + (n * TT + t) * DIM + g * 8;
            pk1 = *(const float4*)Kp; pk2 = *(const float4*)(Kp + 4);
            pv1 = *(const float4*)Vp; pv2 = *(const float4*)(Vp + 4);
        }
        den += a;
        aK[0] += a * k1.x; aK[1] += a * k1.y; aK[2] += a * k1.z; aK[3] += a * k1.w;
        aK[4] += a * k2.x; aK[5] += a * k2.y; aK[6] += a * k2.z; aK[7] += a * k2.w;
        aV[0] += a * v1.x; aV[1] += a * v1.y; aV[2] += a * v1.z; aV[3] += a * v1.w;
        aV[4] += a * v2.x; aV[5] += a * v2.y; aV[6] += a * v2.z; aV[7] += a * v2.w;
    }

    float* pk = g_preK + ((n * NC + c) * SB + s) * DIM + g * 8;
    float* pv = g_preV + ((n * NC + c) * SB + s) * DIM + g * 8;
#pragma unroll
    for (int j = 0; j < 8; j++) { pk[j] = aK[j]; pv[j] = aV[j]; }
    if (g == 0) g_preD[(n * NC + c) * SB + s] = den;
}

// ---------------------------------------------------------------------------
// Phase 3b: exclusive scan over chunks — parallel, register-resident.
// ---------------------------------------------------------------------------
__global__ __launch_bounds__(256) void scan_kernel()
{
    const int idx = blockIdx.x * 256 + threadIdx.x;   // 0..32767
    const int y = blockIdx.y;

    if (y < 2) {
        const int n = idx >> 11;          // /2048
        const int e = idx & 2047;
        float* base = (y == 0 ? g_preK : g_preV) + n * (NC * SB * DIM) + e;
        float v[NC];
#pragma unroll
        for (int c = 0; c < NC; c++) v[c] = base[c * (SB * DIM)];
        float carry = 0.f;
#pragma unroll
        for (int c = 0; c < NC; c++) {
            base[c * (SB * DIM)] = carry;
            carry += v[c];
        }
    } else {
        if (idx < NH * SB) {
            const int n = idx >> 5;
            const int s = idx & 31;
            float* base = g_preD + n * (NC * SB) + s;
            float v[NC];
#pragma unroll
            for (int c = 0; c < NC; c++) v[c] = base[c * SB];
            float carry = 0.f;
#pragma unroll
            for (int c = 0; c < NC; c++) {
                base[c * SB] = carry;
                carry += v[c];
            }
        }
    }
}

// ---------------------------------------------------------------------------
// Phase 4: fused scan-replay + bucket attention — 2 barriers per timestep.
// Softmax computed redundantly in EVERY warp with warp0's exact shfl
// sequence (bit-identical p), fetched per-bucket via intra-warp shfl.
// Loads for t+1 prefetched before the barrier section.
// ---------------------------------------------------------------------------
__global__ __launch_bounds__(256) void attn_kernel()
{
    __shared__ float s_sc[SB];
    __shared__ float s_acc[8][64];

    const int c = blockIdx.x;
    const int n = blockIdx.y;
    const int tid = threadIdx.x;
    const int s = tid >> 3;
    const int g = tid & 7;
    const int warp = tid >> 5;
    const int lane = tid & 31;
    const int b = n >> 3;
    const int h = n & 7;

    float nK[8], nV[8];
    {
        const float* pk = g_preK + ((n * NC + c) * SB + s) * DIM + g * 8;
        const float* pv = g_preV + ((n * NC + c) * SB + s) * DIM + g * 8;
#pragma unroll
        for (int j = 0; j < 8; j++) { nK[j] = pk[j]; nV[j] = pv[j]; }
    }
    float den = g_preD[(n * NC + c) * SB + s];

    const int t0 = c * CH;
    // prefetch t0
    float pa = g_assign[(n * TT + t0) * SB + s];
    const float* Kp0 = g_Kf + (n * TT + t0) * DIM + g * 8;
    const float* Vp0 = g_Vf + (n * TT + t0) * DIM + g * 8;
    const float* Qp0 = g_Qf + (n * TT + t0) * DIM + g * 8;
    float4 pk1 = *(const float4*)Kp0, pk2 = *(const float4*)(Kp0 + 4);
    float4 pv1 = *(const float4*)Vp0, pv2 = *(const float4*)(Vp0 + 4);
    float4 pq1 = *(const float4*)Qp0, pq2 = *(const float4*)(Qp0 + 4);

    for (int tt = 0; tt < CH; tt++) {
        const int t = t0 + tt;
        float a = pa;
        float4 k1 = pk1, k2 = pk2, v1 = pv1, v2 = pv2, q1 = pq1, q2 = pq2;
        if (tt + 1 < CH) {
            const int tn = t + 1;
            pa = g_assign[(n * TT + tn) * SB + s];
            const float* Kp = g_Kf + (n * TT + tn) * DIM + g * 8;
            const float* Vp = g_Vf + (n * TT + tn) * DIM + g * 8;
            const float* Qp = g_Qf + (n * TT + tn) * DIM + g * 8;
            pk1 = *(const float4*)Kp; pk2 = *(const float4*)(Kp + 4);
            pv1 = *(const float4*)Vp; pv2 = *(const float4*)(Vp + 4);
            pq1 = *(const float4*)Qp; pq2 = *(const float4*)(Qp + 4);
        }

        den += a;
        nK[0] += a * k1.x; nK[1] += a * k1.y; nK[2] += a * k1.z; nK[3] += a * k1.w;
        nK[4] += a * k2.x; nK[5] += a * k2.y; nK[6] += a * k2.z; nK[7] += a * k2.w;
        nV[0] += a * v1.x; nV[1] += a * v1.y; nV[2] += a * v1.z; nV[3] += a * v1.w;
        nV[4] += a * v2.x; nV[5] += a * v2.y; nV[6] += a * v2.z; nV[7] += a * v2.w;
        float inv = 1.0f / (den + 1e-6f);

        float part = q1.x * nK[0] + q1.y * nK[1] + q1.z * nK[2] + q1.w * nK[3]
                   + q2.x * nK[4] + q2.y * nK[5] + q2.z * nK[6] + q2.w * nK[7];
        part *= inv * 0.125f;   // 1/sqrt(64)
        part += __shfl_xor_sync(0xffffffffu, part, 1);
        part += __shfl_xor_sync(0xffffffffu, part, 2);
        part += __shfl_xor_sync(0xffffffffu, part, 4);
        if (g == 0) s_sc[s] = part;
        __syncthreads();

        // redundant per-warp softmax — identical op sequence to the old
        // warp0-only version -> bit-identical p in every warp.
        float sc = s_sc[lane];
        float m = sc;
#pragma unroll
        for (int off = 16; off >= 1; off >>= 1)
            m = fmaxf(m, __shfl_xor_sync(0xffffffffu, m, off));
        float e = xla_exp(sc - m);
        float sm = e;
#pragma unroll
        for (int off = 16; off >= 1; off >>= 1)
            sm += __shfl_xor_sync(0xffffffffu, sm, off);
        float p_lane = e / sm;
        float p_s = __shfl_sync(0xffffffffu, p_lane, s & 31);

        float w = p_s * inv;
        float o[8];
#pragma unroll
        for (int j = 0; j < 8; j++) o[j] = w * nV[j];
#pragma unroll
        for (int j = 0; j < 8; j++) {
            o[j] += __shfl_xor_sync(0xffffffffu, o[j], 8);
            o[j] += __shfl_xor_sync(0xffffffffu, o[j], 16);
        }
        if (lane < 8) {
#pragma unroll
            for (int j = 0; j < 8; j++) s_acc[warp][lane * 8 + j] = o[j];
        }
        __syncthreads();

        if (tid < 64) {
            float v = 0.f;
#pragma unroll
            for (int w2 = 0; w2 < 8; w2++) v += s_acc[w2][tid];
            g_att[(b * TT + t) * DM + h * 64 + tid] = v;
        }
    }
}

// ---------------------------------------------------------------------------
extern "C" void kernel_launch(void* const* d_in, const int* in_sizes, int n_in,
                              void* d_out, int out_size)
{
    const float* x          = (const float*)d_in[0];
    const float* Wq         = (const float*)d_in[1];
    const float* Wk         = (const float*)d_in[2];
    const float* Wv         = (const float*)d_in[3];
    const float* Wout       = (const float*)d_in[4];
    const float* bout       = (const float*)d_in[5];
    const float* logit_temp = (const float*)d_in[6];
    const float* planes_T   = (const float*)d_in[7];
    const float* protos_T   = (const float*)d_in[8];
    float* out = (float*)d_out;

    dim3 gqkv(24, 16);   // 1536/64 x 2048/128
    gemm_qkv_kernel<<<gqkv, 256>>>(x, Wq, Wk, Wv);

    assign_kernel<<<64, 256>>>(planes_T, protos_T, logit_temp);

    dim3 gcs(NC, NH);
    chunksum_kernel<<<gcs, 256>>>();

    dim3 gsc(128, 3);    // 32768 (n,e) threads for K and V, 512 for preD
    scan_kernel<<<gsc, 256>>>();

    dim3 gat(NC, NH);
    attn_kernel<<<gat, 256>>>();

    dim3 gout(8, 16);    // 512/64 x 2048/128
    gemm_out_kernel<<<gout, 256>>>(Wout, bout, out);
}

// round 13
// speedup vs baseline: 1.1737x; 1.1737x over previous
#include <cuda_runtime.h>
#include <math.h>

// Problem constants
#define NH     16      // N = B*H
#define TT     1024    // T
#define DIM    64
#define DM     512     // D model
#define LT     4       // tables
#define KBITS  3
#define RB     8       // buckets per table
#define SB     32      // total buckets
#define NC     32      // chunks
#define CH     32      // chunk length (NC*CH = T)

// Scratch (static device globals: no allocation allowed)
__device__ float g_Qf[NH * TT * DIM];
__device__ float g_Kf[NH * TT * DIM];
__device__ float g_Vf[NH * TT * DIM];
__device__ float g_assign[NH * TT * SB];
__device__ float g_preK[NH * NC * SB * DIM];
__device__ float g_preV[NH * NC * SB * DIM];
__device__ float g_preD[NH * NC * SB];
__device__ float g_att[2 * TT * DM];

// Packed dual-FMA: each lane is an independent IEEE fma.rn -> bitwise
// identical to two scalar __fmaf_rn with the same accumulation order.
#define FFMA2(d, a, b, c) \
    asm("fma.rn.f32x2 %0, %1, %2, %3;" : "=l"(d) : "l"(a), "l"(b), "l"(c))
#define BCAST2(d, f) \
    asm("mov.b64 %0, {%1, %1};" : "=l"(d) : "f"(f))

// ---------------------------------------------------------------------------
// XLA-CPU exp(f32): Cephes-style approximation (GenerateVF32Exp).
// ---------------------------------------------------------------------------
__device__ __forceinline__ float xla_exp(float input)
{
    const float exp_hi = 88.3762626647950f;
    const float exp_lo = -88.3762626647949f;
    float xc = fminf(fmaxf(input, exp_lo), exp_hi);
    float fx = floorf(__fmaf_rn(xc, 1.44269504088896341f, 0.5f));
    float tmp = __fmul_rn(fx, 0.693359375f);
    float z   = __fmul_rn(fx, -2.12194440e-4f);
    float x   = __fsub_rn(xc, tmp);
    x         = __fsub_rn(x, z);
    z         = __fmul_rn(x, x);
    float y = __fmaf_rn(x, 1.9875691500e-4f, 1.3981999507e-3f);
    y = __fmaf_rn(y, x, 8.3334519073e-3f);
    y = __fmaf_rn(y, x, 4.1665795894e-2f);
    y = __fmaf_rn(y, x, 1.6666665459e-1f);
    y = __fmaf_rn(y, x, 5.0000001201e-1f);
    y = __fmaf_rn(y, z, x);
    y = __fadd_rn(y, 1.0f);
    int n = (int)fx;
    float scale = __int_as_float((n + 127) << 23);
    return __fmul_rn(y, scale);
}

// ---------------------------------------------------------------------------
// XLA EmitFastTanh with_fma=true (Eigen ptanh pairing): clamp
// +/-7.99881172180175781, FMA Horner, |x|<0.0004 passthrough.
// CONFIRMED (R9 pass): this is the reference's tanh variant.
// ---------------------------------------------------------------------------
__device__ __forceinline__ float xla_tanh(float x)
{
    const float kClamp = 7.99881172180175781f;
    if (fabsf(x) < 0.0004f) return x;
    float xc = fminf(fmaxf(x, -kClamp), kClamp);
    float x2 = __fmul_rn(xc, xc);
    float np = -2.76076847742355e-16f;
    np = __fmaf_rn(np, x2, 2.00018790482477e-13f);
    np = __fmaf_rn(np, x2, -8.60467152213735e-11f);
    np = __fmaf_rn(np, x2, 5.12229709037114e-08f);
    np = __fmaf_rn(np, x2, 1.48572235717979e-05f);
    np = __fmaf_rn(np, x2, 6.37261928875436e-04f);
    np = __fmaf_rn(np, x2, 4.89352455891786e-03f);
    float num = __fmul_rn(xc, np);
    float dp = 1.19825839466702e-06f;
    dp = __fmaf_rn(dp, x2, 1.18534705686654e-04f);
    dp = __fmaf_rn(dp, x2, 2.26843463243900e-03f);
    dp = __fmaf_rn(dp, x2, 4.89352518554385e-03f);
    return __fdiv_rn(num, dp);
}

// ---------------------------------------------------------------------------
// GEMM 1: fused QKV projection, FFMA2 version (unchanged from R11).
// ---------------------------------------------------------------------------
__global__ __launch_bounds__(256) void gemm_qkv_kernel(
    const float* __restrict__ x,
    const float* __restrict__ Wq,
    const float* __restrict__ Wk,
    const float* __restrict__ Wv)
{
    __shared__ __align__(16) float As[16][132];
    __shared__ float Bs[16][68];

    const int j0 = blockIdx.x * 64;     // 0..1535
    const int m0 = blockIdx.y * 128;    // 0..1920
    const int wsel = j0 >> 9;
    const float* W;
    float* outp;
    if (wsel == 0)      { W = Wq; outp = g_Qf; }
    else if (wsel == 1) { W = Wk; outp = g_Kf; }
    else                { W = Wv; outp = g_Vf; }
    const int jj0 = j0 & 511;

    const int tid = threadIdx.x;
    const int tx = tid & 15;
    const int ty = tid >> 4;

    unsigned long long acc2[4][4];
#pragma unroll
    for (int ip = 0; ip < 4; ip++)
#pragma unroll
        for (int j = 0; j < 4; j++) acc2[ip][j] = 0ULL;

    for (int k0 = 0; k0 < 512; k0 += 16) {
#pragma unroll
        for (int i = 0; i < 8; i++) {
            int idx = tid + i * 256;
            int r = idx >> 4;
            int kk = idx & 15;
            As[kk][r] = x[(m0 + r) * 512 + k0 + kk];
        }
#pragma unroll
        for (int i = 0; i < 4; i++) {
            int idx = tid + i * 256;
            int r = idx >> 4;
            int kk = idx & 15;
            Bs[kk][r] = W[(jj0 + r) * 512 + k0 + kk];
        }
        __syncthreads();
#pragma unroll
        for (int kk = 0; kk < 16; kk++) {
            ulonglong2 a01 = *(const ulonglong2*)&As[kk][ty * 8];
            ulonglong2 a23 = *(const ulonglong2*)&As[kk][ty * 8 + 4];
            unsigned long long ap[4] = {a01.x, a01.y, a23.x, a23.y};
#pragma unroll
            for (int j = 0; j < 4; j++) {
                float bj = Bs[kk][tx * 4 + j];
                unsigned long long bb;
                BCAST2(bb, bj);
#pragma unroll
                for (int ip = 0; ip < 4; ip++)
                    FFMA2(acc2[ip][j], ap[ip], bb, acc2[ip][j]);
            }
        }
        __syncthreads();
    }

#pragma unroll
    for (int ip = 0; ip < 4; ip++) {
#pragma unroll
        for (int j = 0; j < 4; j++) {
            float lo = __uint_as_float((unsigned int)(acc2[ip][j] & 0xffffffffULL));
            float hi = __uint_as_float((unsigned int)(acc2[ip][j] >> 32));
            int jc = jj0 + tx * 4 + j;
            int h = jc >> 6;
            int d = jc & 63;
            int m_lo = m0 + ty * 8 + 2 * ip;
            outp[(((m_lo >> 10) * 8 + h) * TT + (m_lo & 1023)) * DIM + d] = lo;
            int m_hi = m_lo + 1;
            outp[(((m_hi >> 10) * 8 + h) * TT + (m_hi & 1023)) * DIM + d] = hi;
        }
    }
}

// ---------------------------------------------------------------------------
// GEMM 2: final output projection, FFMA2 version (unchanged from R11).
// ---------------------------------------------------------------------------
__global__ __launch_bounds__(256) void gemm_out_kernel(
    const float* __restrict__ Wout,
    const float* __restrict__ bout,
    float* __restrict__ out)
{
    __shared__ __align__(16) float As[16][132];
    __shared__ float Bs[16][68];

    const int j0 = blockIdx.x * 64;
    const int m0 = blockIdx.y * 128;
    const int tid = threadIdx.x;
    const int tx = tid & 15;
    const int ty = tid >> 4;

    unsigned long long acc2[4][4];
#pragma unroll
    for (int ip = 0; ip < 4; ip++)
#pragma unroll
        for (int j = 0; j < 4; j++) acc2[ip][j] = 0ULL;

    for (int k0 = 0; k0 < 512; k0 += 16) {
#pragma unroll
        for (int i = 0; i < 8; i++) {
            int idx = tid + i * 256;
            int r = idx >> 4;
            int kk = idx & 15;
            As[kk][r] = g_att[(m0 + r) * 512 + k0 + kk];
        }
#pragma unroll
        for (int i = 0; i < 4; i++) {
            int idx = tid + i * 256;
            int r = idx >> 4;
            int kk = idx & 15;
            Bs[kk][r] = Wout[(j0 + r) * 512 + k0 + kk];
        }
        __syncthreads();
#pragma unroll
        for (int kk = 0; kk < 16; kk++) {
            ulonglong2 a01 = *(const ulonglong2*)&As[kk][ty * 8];
            ulonglong2 a23 = *(const ulonglong2*)&As[kk][ty * 8 + 4];
            unsigned long long ap[4] = {a01.x, a01.y, a23.x, a23.y};
#pragma unroll
            for (int j = 0; j < 4; j++) {
                float bj = Bs[kk][tx * 4 + j];
                unsigned long long bb;
                BCAST2(bb, bj);
#pragma unroll
                for (int ip = 0; ip < 4; ip++)
                    FFMA2(acc2[ip][j], ap[ip], bb, acc2[ip][j]);
            }
        }
        __syncthreads();
    }

#pragma unroll
    for (int ip = 0; ip < 4; ip++) {
#pragma unroll
        for (int j = 0; j < 4; j++) {
            int jc = j0 + tx * 4 + j;
            float bb = bout[jc];
            float lo = __uint_as_float((unsigned int)(acc2[ip][j] & 0xffffffffULL));
            float hi = __uint_as_float((unsigned int)(acc2[ip][j] >> 32));
            int m_lo = m0 + ty * 8 + 2 * ip;
            out[m_lo * 512 + jc]       = __fadd_rn(lo, bb);
            out[(m_lo + 1) * 512 + jc] = __fadd_rn(hi, bb);
        }
    }
}

// ---------------------------------------------------------------------------
// Phase 2: LSH bucket assignment — one thread per (n,t), all 4 tables.
// (kept from R12 — strictly less traffic than one-thread-per-(n,t,l))
// ---------------------------------------------------------------------------
__global__ __launch_bounds__(256) void assign_kernel(
    const float* __restrict__ planes_T,   // [64][12] row-major
    const float* __restrict__ protos_T,   // [3][8]
    const float* __restrict__ logit_temp) // scalar
{
    __shared__ float s_pl[64 * 12];
    __shared__ float s_proto[24];
    const int tid = threadIdx.x;
    for (int i = tid; i < 64 * 12; i += 256) s_pl[i] = planes_T[i];
    if (tid < 24) s_proto[tid] = protos_T[tid];
    __syncthreads();

    const int gid = blockIdx.x * 256 + tid;   // 0..16383
    const int n = gid >> 10;
    const int t = gid & 1023;

    float scale = xla_exp(logit_temp[0]);
    scale = fminf(fmaxf(scale, 0.01f), 20.0f);

    const float4* K4 = (const float4*)(g_Kf + (n * TT + t) * DIM);
    float s[12];
#pragma unroll
    for (int j = 0; j < 12; j++) s[j] = 0.f;

#pragma unroll
    for (int d4 = 0; d4 < 16; d4++) {
        float4 kv4 = K4[d4];
        float kv[4] = {kv4.x, kv4.y, kv4.z, kv4.w};
#pragma unroll
        for (int q = 0; q < 4; q++) {
            const float* pl = s_pl + (d4 * 4 + q) * 12;
#pragma unroll
            for (int j = 0; j < 12; j++)
                s[j] = __fmaf_rn(kv[q], pl[j], s[j]);
        }
    }

    float* outrow = g_assign + (n * TT + t) * SB;
#pragma unroll
    for (int l = 0; l < LT; l++) {
        float t0 = __fdiv_rn(xla_tanh(s[l * 3 + 0]), scale);
        float t1 = __fdiv_rn(xla_tanh(s[l * 3 + 1]), scale);
        float t2 = __fdiv_rn(xla_tanh(s[l * 3 + 2]), scale);

        float logits[RB];
        float mx = -1e30f;
#pragma unroll
        for (int r = 0; r < RB; r++) {
            float lg = __fmaf_rn(t2, s_proto[16 + r],
                       __fmaf_rn(t1, s_proto[8 + r],
                                 __fmul_rn(t0, s_proto[r])));
            logits[r] = lg;
            mx = fmaxf(mx, lg);
        }
        float e[RB];
        float sum = 0.f;
#pragma unroll
        for (int r = 0; r < RB; r++) {
            e[r] = xla_exp(__fsub_rn(logits[r], mx));
            sum = __fadd_rn(sum, e[r]);
        }
        float p[RB];
#pragma unroll
        for (int r = 0; r < RB; r++) p[r] = __fdiv_rn(e[r], sum);

        int i1 = 0; float p1 = p[0];
#pragma unroll
        for (int r = 1; r < RB; r++) { if (p[r] > p1) { p1 = p[r]; i1 = r; } }
        int i2 = -1; float p2 = -1.f;
#pragma unroll
        for (int r = 0; r < RB; r++) { if (r != i1 && p[r] > p2) { p2 = p[r]; i2 = r; } }

        float denom = __fadd_rn(__fadd_rn(p1, p2), 1e-6f);
        float* outp = outrow + l * RB;
#pragma unroll
        for (int r = 0; r < RB; r++) outp[r] = 0.f;
        outp[i1] = __fdiv_rn(p1, denom);
        outp[i2] = __fdiv_rn(p2, denom);
    }
}

// ---------------------------------------------------------------------------
// Phase 3a: per-chunk bucket-state partial sums (R11 version: the a!=0
// guard predicates away ~75% of K/V loads — it is a bandwidth filter).
// ---------------------------------------------------------------------------
__global__ __launch_bounds__(256) void chunksum_kernel()
{
    const int c = blockIdx.x;
    const int n = blockIdx.y;
    const int tid = threadIdx.x;
    const int s = tid >> 3;
    const int g = tid & 7;

    float aK[8], aV[8];
#pragma unroll
    for (int j = 0; j < 8; j++) { aK[j] = 0.f; aV[j] = 0.f; }
    float den = 0.f;

    const int t0 = c * CH;
    for (int tt = 0; tt < CH; tt++) {
        const int t = t0 + tt;
        float a = g_assign[(n * TT + t) * SB + s];
        den += a;
        if (a != 0.f) {
            const float* Kp = g_Kf + (n * TT + t) * DIM + g * 8;
            const float* Vp = g_Vf + (n * TT + t) * DIM + g * 8;
            float4 k1 = *(const float4*)Kp;
            float4 k2 = *(const float4*)(Kp + 4);
            float4 v1 = *(const float4*)Vp;
            float4 v2 = *(const float4*)(Vp + 4);
            aK[0] += a * k1.x; aK[1] += a * k1.y; aK[2] += a * k1.z; aK[3] += a * k1.w;
            aK[4] += a * k2.x; aK[5] += a * k2.y; aK[6] += a * k2.z; aK[7] += a * k2.w;
            aV[0] += a * v1.x; aV[1] += a * v1.y; aV[2] += a * v1.z; aV[3] += a * v1.w;
            aV[4] += a * v2.x; aV[5] += a * v2.y; aV[6] += a * v2.z; aV[7] += a * v2.w;
        }
    }

    float* pk = g_preK + ((n * NC + c) * SB + s) * DIM + g * 8;
    float* pv = g_preV + ((n * NC + c) * SB + s) * DIM + g * 8;
#pragma unroll
    for (int j = 0; j < 8; j++) { pk[j] = aK[j]; pv[j] = aV[j]; }
    if (g == 0) g_preD[(n * NC + c) * SB + s] = den;
}

// ---------------------------------------------------------------------------
// Phase 3b: exclusive scan over chunks — parallel, register-resident.
// ---------------------------------------------------------------------------
__global__ __launch_bounds__(256) void scan_kernel()
{
    const int idx = blockIdx.x * 256 + threadIdx.x;   // 0..32767
    const int y = blockIdx.y;

    if (y < 2) {
        const int n = idx >> 11;          // /2048
        const int e = idx & 2047;
        float* base = (y == 0 ? g_preK : g_preV) + n * (NC * SB * DIM) + e;
        float v[NC];
#pragma unroll
        for (int c = 0; c < NC; c++) v[c] = base[c * (SB * DIM)];
        float carry = 0.f;
#pragma unroll
        for (int c = 0; c < NC; c++) {
            base[c * (SB * DIM)] = carry;
            carry += v[c];
        }
    } else {
        if (idx < NH * SB) {
            const int n = idx >> 5;
            const int s = idx & 31;
            float* base = g_preD + n * (NC * SB) + s;
            float v[NC];
#pragma unroll
            for (int c = 0; c < NC; c++) v[c] = base[c * SB];
            float carry = 0.f;
#pragma unroll
            for (int c = 0; c < NC; c++) {
                base[c * SB] = carry;
                carry += v[c];
            }
        }
    }
}

// ---------------------------------------------------------------------------
// Phase 4: fused scan-replay + bucket attention — guarded K/V loads
// (R11 traffic profile) + 2 barriers per timestep via redundant per-warp
// softmax (bit-identical p in every warp, fetched by intra-warp shfl).
// ---------------------------------------------------------------------------
__global__ __launch_bounds__(256) void attn_kernel()
{
    __shared__ float s_sc[SB];
    __shared__ float s_acc[8][64];

    const int c = blockIdx.x;
    const int n = blockIdx.y;
    const int tid = threadIdx.x;
    const int s = tid >> 3;
    const int g = tid & 7;
    const int warp = tid >> 5;
    const int lane = tid & 31;
    const int b = n >> 3;
    const int h = n & 7;

    float nK[8], nV[8];
    {
        const float* pk = g_preK + ((n * NC + c) * SB + s) * DIM + g * 8;
        const float* pv = g_preV + ((n * NC + c) * SB + s) * DIM + g * 8;
#pragma unroll
        for (int j = 0; j < 8; j++) { nK[j] = pk[j]; nV[j] = pv[j]; }
    }
    float den = g_preD[(n * NC + c) * SB + s];

    const int t0 = c * CH;
    for (int tt = 0; tt < CH; tt++) {
        const int t = t0 + tt;
        float a = g_assign[(n * TT + t) * SB + s];
        den += a;
        const float* Qp = g_Qf + (n * TT + t) * DIM + g * 8;
        if (a != 0.f) {
            const float* Kp = g_Kf + (n * TT + t) * DIM + g * 8;
            const float* Vp = g_Vf + (n * TT + t) * DIM + g * 8;
            float4 k1 = *(const float4*)Kp;
            float4 k2 = *(const float4*)(Kp + 4);
            float4 v1 = *(const float4*)Vp;
            float4 v2 = *(const float4*)(Vp + 4);
            nK[0] += a * k1.x; nK[1] += a * k1.y; nK[2] += a * k1.z; nK[3] += a * k1.w;
            nK[4] += a * k2.x; nK[5] += a * k2.y; nK[6] += a * k2.z; nK[7] += a * k2.w;
            nV[0] += a * v1.x; nV[1] += a * v1.y; nV[2] += a * v1.z; nV[3] += a * v1.w;
            nV[4] += a * v2.x; nV[5] += a * v2.y; nV[6] += a * v2.z; nV[7] += a * v2.w;
        }
        float inv = 1.0f / (den + 1e-6f);

        float4 q1 = *(const float4*)Qp;
        float4 q2 = *(const float4*)(Qp + 4);
        float part = q1.x * nK[0] + q1.y * nK[1] + q1.z * nK[2] + q1.w * nK[3]
                   + q2.x * nK[4] + q2.y * nK[5] + q2.z * nK[6] + q2.w * nK[7];
        part *= inv * 0.125f;   // 1/sqrt(64)
        part += __shfl_xor_sync(0xffffffffu, part, 1);
        part += __shfl_xor_sync(0xffffffffu, part, 2);
        part += __shfl_xor_sync(0xffffffffu, part, 4);
        if (g == 0) s_sc[s] = part;
        __syncthreads();

        // redundant per-warp softmax — identical op sequence to the old
        // warp0-only version -> bit-identical p in every warp.
        float sc = s_sc[lane];
        float m = sc;
#pragma unroll
        for (int off = 16; off >= 1; off >>= 1)
            m = fmaxf(m, __shfl_xor_sync(0xffffffffu, m, off));
        float e = xla_exp(sc - m);
        float sm = e;
#pragma unroll
        for (int off = 16; off >= 1; off >>= 1)
            sm += __shfl_xor_sync(0xffffffffu, sm, off);
        float p_lane = e / sm;
        float p_s = __shfl_sync(0xffffffffu, p_lane, s & 31);

        float w = p_s * inv;
        float o[8];
#pragma unroll
        for (int j = 0; j < 8; j++) o[j] = w * nV[j];
#pragma unroll
        for (int j = 0; j < 8; j++) {
            o[j] += __shfl_xor_sync(0xffffffffu, o[j], 8);
            o[j] += __shfl_xor_sync(0xffffffffu, o[j], 16);
        }
        if (lane < 8) {
#pragma unroll
            for (int j = 0; j < 8; j++) s_acc[warp][lane * 8 + j] = o[j];
        }
        __syncthreads();

        if (tid < 64) {
            float v = 0.f;
#pragma unroll
            for (int w2 = 0; w2 < 8; w2++) v += s_acc[w2][tid];
            g_att[(b * TT + t) * DM + h * 64 + tid] = v;
        }
    }
}

// ---------------------------------------------------------------------------
extern "C" void kernel_launch(void* const* d_in, const int* in_sizes, int n_in,
                              void* d_out, int out_size)
{
    const float* x          = (const float*)d_in[0];
    const float* Wq         = (const float*)d_in[1];
    const float* Wk         = (const float*)d_in[2];
    const float* Wv         = (const float*)d_in[3];
    const float* Wout       = (const float*)d_in[4];
    const float* bout       = (const float*)d_in[5];
    const float* logit_temp = (const float*)d_in[6];
    const float* planes_T   = (const float*)d_in[7];
    const float* protos_T   = (const float*)d_in[8];
    float* out = (float*)d_out;

    dim3 gqkv(24, 16);   // 1536/64 x 2048/128
    gemm_qkv_kernel<<<gqkv, 256>>>(x, Wq, Wk, Wv);

    assign_kernel<<<64, 256>>>(planes_T, protos_T, logit_temp);

    dim3 gcs(NC, NH);
    chunksum_kernel<<<gcs, 256>>>();

    dim3 gsc(128, 3);    // 32768 (n,e) threads for K and V, 512 for preD
    scan_kernel<<<gsc, 256>>>();

    dim3 gat(NC, NH);
    attn_kernel<<<gat, 256>>>();

    dim3 gout(8, 16);    // 512/64 x 2048/128
    gemm_out_kernel<<<gout, 256>>>(Wout, bout, out);
}

// round 14
// speedup vs baseline: 1.1967x; 1.0196x over previous
#include <cuda_runtime.h>
#include <math.h>

// Problem constants
#define NH     16      // N = B*H
#define TT     1024    // T
#define DIM    64
#define DM     512     // D model
#define LT     4       // tables
#define KBITS  3
#define RB     8       // buckets per table
#define SB     32      // total buckets
#define NC     32      // chunks
#define CH     32      // chunk length (NC*CH = T)

// Scratch (static device globals: no allocation allowed)
__device__ float g_Qf[NH * TT * DIM];
__device__ float g_Kf[NH * TT * DIM];
__device__ float g_Vf[NH * TT * DIM];
__device__ float g_assign[NH * TT * SB];
__device__ float g_preK[NH * NC * SB * DIM];
__device__ float g_preV[NH * NC * SB * DIM];
__device__ float g_preD[NH * NC * SB];
__device__ float g_att[2 * TT * DM];

// Packed dual-FMA: each lane is an independent IEEE fma.rn -> bitwise
// identical to two scalar __fmaf_rn with the same accumulation order.
#define FFMA2(d, a, b, c) \
    asm("fma.rn.f32x2 %0, %1, %2, %3;" : "=l"(d) : "l"(a), "l"(b), "l"(c))
#define BCAST2(d, f) \
    asm("mov.b64 %0, {%1, %1};" : "=l"(d) : "f"(f))

// ---------------------------------------------------------------------------
// XLA-CPU exp(f32): Cephes-style approximation (GenerateVF32Exp).
// ---------------------------------------------------------------------------
__device__ __forceinline__ float xla_exp(float input)
{
    const float exp_hi = 88.3762626647950f;
    const float exp_lo = -88.3762626647949f;
    float xc = fminf(fmaxf(input, exp_lo), exp_hi);
    float fx = floorf(__fmaf_rn(xc, 1.44269504088896341f, 0.5f));
    float tmp = __fmul_rn(fx, 0.693359375f);
    float z   = __fmul_rn(fx, -2.12194440e-4f);
    float x   = __fsub_rn(xc, tmp);
    x         = __fsub_rn(x, z);
    z         = __fmul_rn(x, x);
    float y = __fmaf_rn(x, 1.9875691500e-4f, 1.3981999507e-3f);
    y = __fmaf_rn(y, x, 8.3334519073e-3f);
    y = __fmaf_rn(y, x, 4.1665795894e-2f);
    y = __fmaf_rn(y, x, 1.6666665459e-1f);
    y = __fmaf_rn(y, x, 5.0000001201e-1f);
    y = __fmaf_rn(y, z, x);
    y = __fadd_rn(y, 1.0f);
    int n = (int)fx;
    float scale = __int_as_float((n + 127) << 23);
    return __fmul_rn(y, scale);
}

// ---------------------------------------------------------------------------
// XLA EmitFastTanh with_fma=true (Eigen ptanh pairing): clamp
// +/-7.99881172180175781, FMA Horner, |x|<0.0004 passthrough.
// CONFIRMED (R9 pass): this is the reference's tanh variant.
// ---------------------------------------------------------------------------
__device__ __forceinline__ float xla_tanh(float x)
{
    const float kClamp = 7.99881172180175781f;
    if (fabsf(x) < 0.0004f) return x;
    float xc = fminf(fmaxf(x, -kClamp), kClamp);
    float x2 = __fmul_rn(xc, xc);
    float np = -2.76076847742355e-16f;
    np = __fmaf_rn(np, x2, 2.00018790482477e-13f);
    np = __fmaf_rn(np, x2, -8.60467152213735e-11f);
    np = __fmaf_rn(np, x2, 5.12229709037114e-08f);
    np = __fmaf_rn(np, x2, 1.48572235717979e-05f);
    np = __fmaf_rn(np, x2, 6.37261928875436e-04f);
    np = __fmaf_rn(np, x2, 4.89352455891786e-03f);
    float num = __fmul_rn(xc, np);
    float dp = 1.19825839466702e-06f;
    dp = __fmaf_rn(dp, x2, 1.18534705686654e-04f);
    dp = __fmaf_rn(dp, x2, 2.26843463243900e-03f);
    dp = __fmaf_rn(dp, x2, 4.89352518554385e-03f);
    return __fdiv_rn(num, dp);
}

// ---------------------------------------------------------------------------
// GEMM 1: fused QKV projection, FFMA2 + double-buffered smem.
// Block tile 128(M)x64(N), 256 threads, thread tile 8x4 as row-pairs.
// Same ascending-k accumulation chains as R11/R13 -> bit-identical output.
// ---------------------------------------------------------------------------
__global__ __launch_bounds__(256) void gemm_qkv_kernel(
    const float* __restrict__ x,
    const float* __restrict__ Wq,
    const float* __restrict__ Wk,
    const float* __restrict__ Wv)
{
    __shared__ __align__(16) float As[2][16][132];
    __shared__ float Bs[2][16][68];

    const int j0 = blockIdx.x * 64;     // 0..1535
    const int m0 = blockIdx.y * 128;    // 0..1920
    const int wsel = j0 >> 9;
    const float* W;
    float* outp;
    if (wsel == 0)      { W = Wq; outp = g_Qf; }
    else if (wsel == 1) { W = Wk; outp = g_Kf; }
    else                { W = Wv; outp = g_Vf; }
    const int jj0 = j0 & 511;

    const int tid = threadIdx.x;
    const int tx = tid & 15;
    const int ty = tid >> 4;
    const int lr = tid >> 4;        // load row base (same decomposition)
    const int lk = tid & 15;

    unsigned long long acc2[4][4];
#pragma unroll
    for (int ip = 0; ip < 4; ip++)
#pragma unroll
        for (int j = 0; j < 4; j++) acc2[ip][j] = 0ULL;

    // preload tile 0
#pragma unroll
    for (int i = 0; i < 8; i++)
        As[0][lk][lr + i * 16] = x[(m0 + lr + i * 16) * 512 + lk];
#pragma unroll
    for (int i = 0; i < 4; i++)
        Bs[0][lk][lr + i * 16] = W[(jj0 + lr + i * 16) * 512 + lk];
    __syncthreads();

    float ra[8], rb[4];
    for (int tile = 0; tile < 32; tile++) {
        const int buf = tile & 1;
        if (tile < 31) {
            const int k0n = (tile + 1) * 16;
#pragma unroll
            for (int i = 0; i < 8; i++)
                ra[i] = x[(m0 + lr + i * 16) * 512 + k0n + lk];
#pragma unroll
            for (int i = 0; i < 4; i++)
                rb[i] = W[(jj0 + lr + i * 16) * 512 + k0n + lk];
        }
#pragma unroll
        for (int kk = 0; kk < 16; kk++) {
            ulonglong2 a01 = *(const ulonglong2*)&As[buf][kk][ty * 8];
            ulonglong2 a23 = *(const ulonglong2*)&As[buf][kk][ty * 8 + 4];
            unsigned long long ap[4] = {a01.x, a01.y, a23.x, a23.y};
#pragma unroll
            for (int j = 0; j < 4; j++) {
                float bj = Bs[buf][kk][tx * 4 + j];
                unsigned long long bb;
                BCAST2(bb, bj);
#pragma unroll
                for (int ip = 0; ip < 4; ip++)
                    FFMA2(acc2[ip][j], ap[ip], bb, acc2[ip][j]);
            }
        }
        if (tile < 31) {
            const int nb = buf ^ 1;
#pragma unroll
            for (int i = 0; i < 8; i++)
                As[nb][lk][lr + i * 16] = ra[i];
#pragma unroll
            for (int i = 0; i < 4; i++)
                Bs[nb][lk][lr + i * 16] = rb[i];
        }
        __syncthreads();
    }

#pragma unroll
    for (int ip = 0; ip < 4; ip++) {
#pragma unroll
        for (int j = 0; j < 4; j++) {
            float lo = __uint_as_float((unsigned int)(acc2[ip][j] & 0xffffffffULL));
            float hi = __uint_as_float((unsigned int)(acc2[ip][j] >> 32));
            int jc = jj0 + tx * 4 + j;
            int h = jc >> 6;
            int d = jc & 63;
            int m_lo = m0 + ty * 8 + 2 * ip;
            outp[(((m_lo >> 10) * 8 + h) * TT + (m_lo & 1023)) * DIM + d] = lo;
            int m_hi = m_lo + 1;
            outp[(((m_hi >> 10) * 8 + h) * TT + (m_hi & 1023)) * DIM + d] = hi;
        }
    }
}

// ---------------------------------------------------------------------------
// GEMM 2: final output projection, FFMA2 + double-buffered smem.
// ---------------------------------------------------------------------------
__global__ __launch_bounds__(256) void gemm_out_kernel(
    const float* __restrict__ Wout,
    const float* __restrict__ bout,
    float* __restrict__ out)
{
    __shared__ __align__(16) float As[2][16][132];
    __shared__ float Bs[2][16][68];

    const int j0 = blockIdx.x * 64;
    const int m0 = blockIdx.y * 128;
    const int tid = threadIdx.x;
    const int tx = tid & 15;
    const int ty = tid >> 4;
    const int lr = tid >> 4;
    const int lk = tid & 15;

    unsigned long long acc2[4][4];
#pragma unroll
    for (int ip = 0; ip < 4; ip++)
#pragma unroll
        for (int j = 0; j < 4; j++) acc2[ip][j] = 0ULL;

#pragma unroll
    for (int i = 0; i < 8; i++)
        As[0][lk][lr + i * 16] = g_att[(m0 + lr + i * 16) * 512 + lk];
#pragma unroll
    for (int i = 0; i < 4; i++)
        Bs[0][lk][lr + i * 16] = Wout[(j0 + lr + i * 16) * 512 + lk];
    __syncthreads();

    float ra[8], rb[4];
    for (int tile = 0; tile < 32; tile++) {
        const int buf = tile & 1;
        if (tile < 31) {
            const int k0n = (tile + 1) * 16;
#pragma unroll
            for (int i = 0; i < 8; i++)
                ra[i] = g_att[(m0 + lr + i * 16) * 512 + k0n + lk];
#pragma unroll
            for (int i = 0; i < 4; i++)
                rb[i] = Wout[(j0 + lr + i * 16) * 512 + k0n + lk];
        }
#pragma unroll
        for (int kk = 0; kk < 16; kk++) {
            ulonglong2 a01 = *(const ulonglong2*)&As[buf][kk][ty * 8];
            ulonglong2 a23 = *(const ulonglong2*)&As[buf][kk][ty * 8 + 4];
            unsigned long long ap[4] = {a01.x, a01.y, a23.x, a23.y};
#pragma unroll
            for (int j = 0; j < 4; j++) {
                float bj = Bs[buf][kk][tx * 4 + j];
                unsigned long long bb;
                BCAST2(bb, bj);
#pragma unroll
                for (int ip = 0; ip < 4; ip++)
                    FFMA2(acc2[ip][j], ap[ip], bb, acc2[ip][j]);
            }
        }
        if (tile < 31) {
            const int nb = buf ^ 1;
#pragma unroll
            for (int i = 0; i < 8; i++)
                As[nb][lk][lr + i * 16] = ra[i];
#pragma unroll
            for (int i = 0; i < 4; i++)
                Bs[nb][lk][lr + i * 16] = rb[i];
        }
        __syncthreads();
    }

#pragma unroll
    for (int ip = 0; ip < 4; ip++) {
#pragma unroll
        for (int j = 0; j < 4; j++) {
            int jc = j0 + tx * 4 + j;
            float bb = bout[jc];
            float lo = __uint_as_float((unsigned int)(acc2[ip][j] & 0xffffffffULL));
            float hi = __uint_as_float((unsigned int)(acc2[ip][j] >> 32));
            int m_lo = m0 + ty * 8 + 2 * ip;
            out[m_lo * 512 + jc]       = __fadd_rn(lo, bb);
            out[(m_lo + 1) * 512 + jc] = __fadd_rn(hi, bb);
        }
    }
}

// ---------------------------------------------------------------------------
// Phase 2: LSH bucket assignment — one thread per (n,t), all 4 tables.
// ---------------------------------------------------------------------------
__global__ __launch_bounds__(256) void assign_kernel(
    const float* __restrict__ planes_T,   // [64][12] row-major
    const float* __restrict__ protos_T,   // [3][8]
    const float* __restrict__ logit_temp) // scalar
{
    __shared__ float s_pl[64 * 12];
    __shared__ float s_proto[24];
    const int tid = threadIdx.x;
    for (int i = tid; i < 64 * 12; i += 256) s_pl[i] = planes_T[i];
    if (tid < 24) s_proto[tid] = protos_T[tid];
    __syncthreads();

    const int gid = blockIdx.x * 256 + tid;   // 0..16383
    const int n = gid >> 10;
    const int t = gid & 1023;

    float scale = xla_exp(logit_temp[0]);
    scale = fminf(fmaxf(scale, 0.01f), 20.0f);

    const float4* K4 = (const float4*)(g_Kf + (n * TT + t) * DIM);
    float s[12];
#pragma unroll
    for (int j = 0; j < 12; j++) s[j] = 0.f;

#pragma unroll
    for (int d4 = 0; d4 < 16; d4++) {
        float4 kv4 = K4[d4];
        float kv[4] = {kv4.x, kv4.y, kv4.z, kv4.w};
#pragma unroll
        for (int q = 0; q < 4; q++) {
            const float* pl = s_pl + (d4 * 4 + q) * 12;
#pragma unroll
            for (int j = 0; j < 12; j++)
                s[j] = __fmaf_rn(kv[q], pl[j], s[j]);
        }
    }

    float* outrow = g_assign + (n * TT + t) * SB;
#pragma unroll
    for (int l = 0; l < LT; l++) {
        float t0 = __fdiv_rn(xla_tanh(s[l * 3 + 0]), scale);
        float t1 = __fdiv_rn(xla_tanh(s[l * 3 + 1]), scale);
        float t2 = __fdiv_rn(xla_tanh(s[l * 3 + 2]), scale);

        float logits[RB];
        float mx = -1e30f;
#pragma unroll
        for (int r = 0; r < RB; r++) {
            float lg = __fmaf_rn(t2, s_proto[16 + r],
                       __fmaf_rn(t1, s_proto[8 + r],
                                 __fmul_rn(t0, s_proto[r])));
            logits[r] = lg;
            mx = fmaxf(mx, lg);
        }
        float e[RB];
        float sum = 0.f;
#pragma unroll
        for (int r = 0; r < RB; r++) {
            e[r] = xla_exp(__fsub_rn(logits[r], mx));
            sum = __fadd_rn(sum, e[r]);
        }
        float p[RB];
#pragma unroll
        for (int r = 0; r < RB; r++) p[r] = __fdiv_rn(e[r], sum);

        int i1 = 0; float p1 = p[0];
#pragma unroll
        for (int r = 1; r < RB; r++) { if (p[r] > p1) { p1 = p[r]; i1 = r; } }
        int i2 = -1; float p2 = -1.f;
#pragma unroll
        for (int r = 0; r < RB; r++) { if (r != i1 && p[r] > p2) { p2 = p[r]; i2 = r; } }

        float denom = __fadd_rn(__fadd_rn(p1, p2), 1e-6f);
        float* outp = outrow + l * RB;
#pragma unroll
        for (int r = 0; r < RB; r++) outp[r] = 0.f;
        outp[i1] = __fdiv_rn(p1, denom);
        outp[i2] = __fdiv_rn(p2, denom);
    }
}

// ---------------------------------------------------------------------------
// Phase 3a: per-chunk bucket-state partial sums (guarded loads — the a!=0
// guard predicates away ~75% of K/V loads; it is a bandwidth filter).
// ---------------------------------------------------------------------------
__global__ __launch_bounds__(256) void chunksum_kernel()
{
    const int c = blockIdx.x;
    const int n = blockIdx.y;
    const int tid = threadIdx.x;
    const int s = tid >> 3;
    const int g = tid & 7;

    float aK[8], aV[8];
#pragma unroll
    for (int j = 0; j < 8; j++) { aK[j] = 0.f; aV[j] = 0.f; }
    float den = 0.f;

    const int t0 = c * CH;
    for (int tt = 0; tt < CH; tt++) {
        const int t = t0 + tt;
        float a = g_assign[(n * TT + t) * SB + s];
        den += a;
        if (a != 0.f) {
            const float* Kp = g_Kf + (n * TT + t) * DIM + g * 8;
            const float* Vp = g_Vf + (n * TT + t) * DIM + g * 8;
            float4 k1 = *(const float4*)Kp;
            float4 k2 = *(const float4*)(Kp + 4);
            float4 v1 = *(const float4*)Vp;
            float4 v2 = *(const float4*)(Vp + 4);
            aK[0] += a * k1.x; aK[1] += a * k1.y; aK[2] += a * k1.z; aK[3] += a * k1.w;
            aK[4] += a * k2.x; aK[5] += a * k2.y; aK[6] += a * k2.z; aK[7] += a * k2.w;
            aV[0] += a * v1.x; aV[1] += a * v1.y; aV[2] += a * v1.z; aV[3] += a * v1.w;
            aV[4] += a * v2.x; aV[5] += a * v2.y; aV[6] += a * v2.z; aV[7] += a * v2.w;
        }
    }

    float* pk = g_preK + ((n * NC + c) * SB + s) * DIM + g * 8;
    float* pv = g_preV + ((n * NC + c) * SB + s) * DIM + g * 8;
#pragma unroll
    for (int j = 0; j < 8; j++) { pk[j] = aK[j]; pv[j] = aV[j]; }
    if (g == 0) g_preD[(n * NC + c) * SB + s] = den;
}

// ---------------------------------------------------------------------------
// Phase 3b: exclusive scan over chunks — parallel, register-resident.
// ---------------------------------------------------------------------------
__global__ __launch_bounds__(256) void scan_kernel()
{
    const int idx = blockIdx.x * 256 + threadIdx.x;   // 0..32767
    const int y = blockIdx.y;

    if (y < 2) {
        const int n = idx >> 11;          // /2048
        const int e = idx & 2047;
        float* base = (y == 0 ? g_preK : g_preV) + n * (NC * SB * DIM) + e;
        float v[NC];
#pragma unroll
        for (int c = 0; c < NC; c++) v[c] = base[c * (SB * DIM)];
        float carry = 0.f;
#pragma unroll
        for (int c = 0; c < NC; c++) {
            base[c * (SB * DIM)] = carry;
            carry += v[c];
        }
    } else {
        if (idx < NH * SB) {
            const int n = idx >> 5;
            const int s = idx & 31;
            float* base = g_preD + n * (NC * SB) + s;
            float v[NC];
#pragma unroll
            for (int c = 0; c < NC; c++) v[c] = base[c * SB];
            float carry = 0.f;
#pragma unroll
            for (int c = 0; c < NC; c++) {
                base[c * SB] = carry;
                carry += v[c];
            }
        }
    }
}

// ---------------------------------------------------------------------------
// Phase 4: fused scan-replay + bucket attention — guarded K/V loads +
// 2 barriers per timestep via redundant per-warp softmax.
// ---------------------------------------------------------------------------
__global__ __launch_bounds__(256) void attn_kernel()
{
    __shared__ float s_sc[SB];
    __shared__ float s_acc[8][64];

    const int c = blockIdx.x;
    const int n = blockIdx.y;
    const int tid = threadIdx.x;
    const int s = tid >> 3;
    const int g = tid & 7;
    const int warp = tid >> 5;
    const int lane = tid & 31;
    const int b = n >> 3;
    const int h = n & 7;

    float nK[8], nV[8];
    {
        const float* pk = g_preK + ((n * NC + c) * SB + s) * DIM + g * 8;
        const float* pv = g_preV + ((n * NC + c) * SB + s) * DIM + g * 8;
#pragma unroll
        for (int j = 0; j < 8; j++) { nK[j] = pk[j]; nV[j] = pv[j]; }
    }
    float den = g_preD[(n * NC + c) * SB + s];

    const int t0 = c * CH;
    for (int tt = 0; tt < CH; tt++) {
        const int t = t0 + tt;
        float a = g_assign[(n * TT + t) * SB + s];
        den += a;
        const float* Qp = g_Qf + (n * TT + t) * DIM + g * 8;
        if (a != 0.f) {
            const float* Kp = g_Kf + (n * TT + t) * DIM + g * 8;
            const float* Vp = g_Vf + (n * TT + t) * DIM + g * 8;
            float4 k1 = *(const float4*)Kp;
            float4 k2 = *(const float4*)(Kp + 4);
            float4 v1 = *(const float4*)Vp;
            float4 v2 = *(const float4*)(Vp + 4);
            nK[0] += a * k1.x; nK[1] += a * k1.y; nK[2] += a * k1.z; nK[3] += a * k1.w;
            nK[4] += a * k2.x; nK[5] += a * k2.y; nK[6] += a * k2.z; nK[7] += a * k2.w;
            nV[0] += a * v1.x; nV[1] += a * v1.y; nV[2] += a * v1.z; nV[3] += a * v1.w;
            nV[4] += a * v2.x; nV[5] += a * v2.y; nV[6] += a * v2.z; nV[7] += a * v2.w;
        }
        float inv = 1.0f / (den + 1e-6f);

        float4 q1 = *(const float4*)Qp;
        float4 q2 = *(const float4*)(Qp + 4);
        float part = q1.x * nK[0] + q1.y * nK[1] + q1.z * nK[2] + q1.w * nK[3]
                   + q2.x * nK[4] + q2.y * nK[5] + q2.z * nK[6] + q2.w * nK[7];
        part *= inv * 0.125f;   // 1/sqrt(64)
        part += __shfl_xor_sync(0xffffffffu, part, 1);
        part += __shfl_xor_sync(0xffffffffu, part, 2);
        part += __shfl_xor_sync(0xffffffffu, part, 4);
        if (g == 0) s_sc[s] = part;
        __syncthreads();

        // redundant per-warp softmax — identical op sequence to the original
        // warp0-only version -> bit-identical p in every warp.
        float sc = s_sc[lane];
        float m = sc;
#pragma unroll
        for (int off = 16; off >= 1; off >>= 1)
            m = fmaxf(m, __shfl_xor_sync(0xffffffffu, m, off));
        float e = xla_exp(sc - m);
        float sm = e;
#pragma unroll
        for (int off = 16; off >= 1; off >>= 1)
            sm += __shfl_xor_sync(0xffffffffu, sm, off);
        float p_lane = e / sm;
        float p_s = __shfl_sync(0xffffffffu, p_lane, s & 31);

        float w = p_s * inv;
        float o[8];
#pragma unroll
        for (int j = 0; j < 8; j++) o[j] = w * nV[j];
#pragma unroll
        for (int j = 0; j < 8; j++) {
            o[j] += __shfl_xor_sync(0xffffffffu, o[j], 8);
            o[j] += __shfl_xor_sync(0xffffffffu, o[j], 16);
        }
        if (lane < 8) {
#pragma unroll
            for (int j = 0; j < 8; j++) s_acc[warp][lane * 8 + j] = o[j];
        }
        __syncthreads();

        if (tid < 64) {
            float v = 0.f;
#pragma unroll
            for (int w2 = 0; w2 < 8; w2++) v += s_acc[w2][tid];
            g_att[(b * TT + t) * DM + h * 64 + tid] = v;
        }
    }
}

// ---------------------------------------------------------------------------
extern "C" void kernel_launch(void* const* d_in, const int* in_sizes, int n_in,
                              void* d_out, int out_size)
{
    const float* x          = (const float*)d_in[0];
    const float* Wq         = (const float*)d_in[1];
    const float* Wk         = (const float*)d_in[2];
    const float* Wv         = (const float*)d_in[3];
    const float* Wout       = (const float*)d_in[4];
    const float* bout       = (const float*)d_in[5];
    const float* logit_temp = (const float*)d_in[6];
    const float* planes_T   = (const float*)d_in[7];
    const float* protos_T   = (const float*)d_in[8];
    float* out = (float*)d_out;

    dim3 gqkv(24, 16);   // 1536/64 x 2048/128
    gemm_qkv_kernel<<<gqkv, 256>>>(x, Wq, Wk, Wv);

    assign_kernel<<<64, 256>>>(planes_T, protos_T, logit_temp);

    dim3 gcs(NC, NH);
    chunksum_kernel<<<gcs, 256>>>();

    dim3 gsc(128, 3);    // 32768 (n,e) threads for K and V, 512 for preD
    scan_kernel<<<gsc, 256>>>();

    dim3 gat(NC, NH);
    attn_kernel<<<gat, 256>>>();

    dim3 gout(8, 16);    // 512/64 x 2048/128
    gemm_out_kernel<<<gout, 256>>>(Wout, bout, out);
}